// round 4
// baseline (speedup 1.0000x reference)
#include <cuda_runtime.h>
#include <cstddef>

// ---------------------------------------------------------------------------
// Depthwise Gaussian blur, sigma=7, K=29, reflect padding, (8,64,256,256) f32.
// Separable: out = Gv * (Gh * x). Fused single kernel:
//   phase 1: load 92 input rows (vertical reflect) into smem
//   phase 2: vertical 29-tap conv, in-place (2-chunk schedule)
//   phase 2.5: fill 16-float reflected horizontal halo per row
//   phase 3: horizontal 29-tap conv, 4 px/lane, coalesced float4 stores
// Weights are compile-time literals -> FFMA with immediate multiplier.
// ---------------------------------------------------------------------------

#define IMG_H   256
#define IMG_W   256
#define TY      64            // output rows per tile
#define RAD     14
#define IR      (TY + 2*RAD)  // 92 input rows in smem
#define PITCH   288           // floats per smem row (16 halo + 256 + 16 halo)
#define XOFF    16            // float offset of x=0 within a smem row
#define SMEM_BYTES (IR * PITCH * 4)   // 105984

// Unnormalized Gaussian g(d) = exp(-d^2/98), d = 0..14 (double literals).
constexpr double GV0  = 1.0;
constexpr double GV1  = 0.98984780;
constexpr double GV2  = 0.96000544;
constexpr double GV3  = 0.91225408;
constexpr double GV4  = 0.84936582;
constexpr double GV5  = 0.77483743;
constexpr double GV6  = 0.69256933;
constexpr double GV7  = 0.60653066;
constexpr double GV8  = 0.52045018;
constexpr double GV9  = 0.43756464;
constexpr double GV10 = 0.36044780;
constexpr double GV11 = 0.29092383;
constexpr double GV12 = 0.23006630;
constexpr double GV13 = 0.17826390;
constexpr double GV14 = 0.13533528;

constexpr double GSUM = GV0 + 2.0*(GV1+GV2+GV3+GV4+GV5+GV6+GV7+GV8+GV9+GV10+GV11+GV12+GV13+GV14);

// Normalized 1D weights, symmetric, index k = 0..28 (tap offset k-14).
__device__ constexpr float GW[29] = {
    (float)(GV14/GSUM), (float)(GV13/GSUM), (float)(GV12/GSUM), (float)(GV11/GSUM),
    (float)(GV10/GSUM), (float)(GV9 /GSUM), (float)(GV8 /GSUM), (float)(GV7 /GSUM),
    (float)(GV6 /GSUM), (float)(GV5 /GSUM), (float)(GV4 /GSUM), (float)(GV3 /GSUM),
    (float)(GV2 /GSUM), (float)(GV1 /GSUM), (float)(GV0 /GSUM), (float)(GV1 /GSUM),
    (float)(GV2 /GSUM), (float)(GV3 /GSUM), (float)(GV4 /GSUM), (float)(GV5 /GSUM),
    (float)(GV6 /GSUM), (float)(GV7 /GSUM), (float)(GV8 /GSUM), (float)(GV9 /GSUM),
    (float)(GV10/GSUM), (float)(GV11/GSUM), (float)(GV12/GSUM), (float)(GV13/GSUM),
    (float)(GV14/GSUM)
};

__global__ void __launch_bounds__(256, 2)
gauss29_kernel(const float* __restrict__ x, float* __restrict__ out)
{
    extern __shared__ float S[];   // [IR][PITCH]

    const int tid  = threadIdx.x;
    const int img  = blockIdx.x >> 2;      // 512 images
    const int tile = blockIdx.x & 3;       // 4 row-tiles per image
    const int y0   = tile * TY;

    const float* src = x   + (size_t)img * (IMG_H * IMG_W);
    float*       dst = out + (size_t)img * (IMG_H * IMG_W) + (size_t)y0 * IMG_W;

    // ---------------- Phase 1: load 92 rows with vertical reflect -----------
    // 92 rows * 64 quads = 5888 float4 loads; 23 per thread, coalesced.
    #pragma unroll 4
    for (int u = tid; u < IR * 64; u += 256) {
        int r  = u >> 6;
        int c4 = u & 63;
        int gy = y0 - RAD + r;
        gy = (gy < 0) ? -gy : gy;
        gy = (gy > IMG_H - 1) ? (2 * (IMG_H - 1) - gy) : gy;
        float4 v = *((const float4*)(src + (size_t)gy * IMG_W) + c4);
        *(float4*)(&S[r * PITCH + XOFF + c4 * 4]) = v;
    }
    __syncthreads();

    // ---------------- Phase 2: vertical 29-tap conv, in place ---------------
    // Output local row j taps smem rows j..j+28.  Two chunks of 32 rows:
    // chunk reads rows [cbase, cbase+60), then (after barrier) overwrites
    // rows [cbase, cbase+32) -- never read again by the later chunk.
    const int xq = tid & 63;          // quad column 0..63
    const int yr = (tid >> 6) * 8;    // 0,8,16,24 within chunk
    #pragma unroll 1
    for (int ch = 0; ch < 2; ++ch) {
        const int ybase = ch * 32 + yr;
        float4 acc[8];
        #pragma unroll
        for (int j = 0; j < 8; ++j) acc[j] = make_float4(0.f, 0.f, 0.f, 0.f);

        const float* col = &S[ybase * PITCH + XOFF + xq * 4];
        #pragma unroll
        for (int i = 0; i < 36; ++i) {
            float4 v = *(const float4*)(col + i * PITCH);
            #pragma unroll
            for (int j = 0; j < 8; ++j) {
                const int k = i - j;               // tap index
                if (k >= 0 && k <= 28) {
                    const float w = GW[k];         // compile-time constant
                    acc[j].x += w * v.x;
                    acc[j].y += w * v.y;
                    acc[j].z += w * v.z;
                    acc[j].w += w * v.w;
                }
            }
        }
        __syncthreads();   // all reads of this chunk done everywhere
        float* od = &S[ybase * PITCH + XOFF + xq * 4];
        #pragma unroll
        for (int j = 0; j < 8; ++j)
            *(float4*)(od + j * PITCH) = acc[j];
        __syncthreads();   // writes visible before next chunk reads
    }

    // ---------------- Phase 2.5: horizontal reflected halo ------------------
    // Fill float cols [0,16) (xi=-16..-1 -> x=16..1) and [272,288)
    // (xi=256..271 -> x=254..239) for the 64 intermediate rows.
    #pragma unroll 1
    for (int u = tid; u < TY * 32; u += 256) {
        int r = u >> 5;
        int p = u & 31;
        int colidx, xsrc;
        if (p < 16) { colidx = p;                 xsrc = 16 - p;      }
        else        { int q = p - 16; colidx = XOFF + 256 + q; xsrc = 254 - q; }
        S[r * PITCH + colidx] = S[r * PITCH + XOFF + xsrc];
    }
    __syncthreads();

    // ---------------- Phase 3: horizontal 29-tap conv + store ---------------
    // Warp-unit = 128 px (half a row); lane covers 4 consecutive px.
    // Window = 9 float4 (36 floats), lane-stride 16B -> conflict-free LDS.128.
    const int lane = tid & 31;
    const int warp = tid >> 5;        // 0..7
    #pragma unroll 1
    for (int it = 0; it < 16; ++it) {
        const int unit = warp * 16 + it;     // 0..127
        const int row  = unit >> 1;
        const int half = unit & 1;
        // base output x = half*128 + lane*4 ; window floats xi = x-16 .. x+19
        // smem col of xi = XOFF + xi  ->  starts at  half*128 + lane*4
        const float* rp = &S[row * PITCH + half * 128 + lane * 4];

        float f[36];
        #pragma unroll
        for (int t = 0; t < 9; ++t) {
            float4 v = *(const float4*)(rp + t * 4);
            f[t * 4 + 0] = v.x; f[t * 4 + 1] = v.y;
            f[t * 4 + 2] = v.z; f[t * 4 + 3] = v.w;
        }

        float a0 = 0.f, a1 = 0.f, a2 = 0.f, a3 = 0.f;
        #pragma unroll
        for (int k = 0; k < 29; ++k) {
            const float w = GW[k];
            a0 += w * f[k + 2];
            a1 += w * f[k + 3];
            a2 += w * f[k + 4];
            a3 += w * f[k + 5];
        }

        *(float4*)(dst + (size_t)row * IMG_W + half * 128 + lane * 4) =
            make_float4(a0, a1, a2, a3);
    }
}

extern "C" void kernel_launch(void* const* d_in, const int* in_sizes, int n_in,
                              void* d_out, int out_size)
{
    const float* x = (const float*)d_in[0];
    float* out = (float*)d_out;

    // images = N*C; each image is 256x256, 4 row-tiles per image.
    const int images = in_sizes[0] / (IMG_H * IMG_W);   // 512
    const int grid = images * 4;                        // 2048 CTAs

    cudaFuncSetAttribute(gauss29_kernel,
                         cudaFuncAttributeMaxDynamicSharedMemorySize,
                         SMEM_BYTES);
    gauss29_kernel<<<grid, 256, SMEM_BYTES>>>(x, out);
}

// round 7
// speedup vs baseline: 1.0738x; 1.0738x over previous
#include <cuda_runtime.h>
#include <cstddef>

// ---------------------------------------------------------------------------
// Depthwise Gaussian blur, sigma=7, K=29, reflect padding, (8,64,256,256) f32.
// Separable, fused single kernel. R4 change: phase-3 does 8 px/lane
// (10 LDS.128 per 8 outputs instead of 9 per 4), with an XOR-4 quad swizzle
// on the smem row layout to keep all LDS.128 phases bank-conflict-free.
// ---------------------------------------------------------------------------

#define IMG_H   256
#define IMG_W   256
#define TY      64            // output rows per tile
#define RAD     14
#define IR      (TY + 2*RAD)  // 92 input rows in smem
#define PITCH   288           // floats per smem row (16 halo + 256 + 16 halo)
#define XOFF    16            // float offset of x=0 within a smem row
#define SMEM_BYTES (IR * PITCH * 4)   // 105984

// Quad swizzle: XOR float-offset bit2 with bit5 (moves whole float4 blocks,
// bijective, within-row). Makes 32B-lane-stride LDS.128 conflict-free while
// keeping 16B-lane-stride accesses conflict-free too.
__device__ __forceinline__ int swz(int o) { return o ^ ((o & 32) >> 3); }

// Unnormalized Gaussian g(d) = exp(-d^2/98), d = 0..14 (double literals).
constexpr double GV0  = 1.0;
constexpr double GV1  = 0.98984780;
constexpr double GV2  = 0.96000544;
constexpr double GV3  = 0.91225408;
constexpr double GV4  = 0.84936582;
constexpr double GV5  = 0.77483743;
constexpr double GV6  = 0.69256933;
constexpr double GV7  = 0.60653066;
constexpr double GV8  = 0.52045018;
constexpr double GV9  = 0.43756464;
constexpr double GV10 = 0.36044780;
constexpr double GV11 = 0.29092383;
constexpr double GV12 = 0.23006630;
constexpr double GV13 = 0.17826390;
constexpr double GV14 = 0.13533528;

constexpr double GSUM = GV0 + 2.0*(GV1+GV2+GV3+GV4+GV5+GV6+GV7+GV8+GV9+GV10+GV11+GV12+GV13+GV14);

__device__ constexpr float GW[29] = {
    (float)(GV14/GSUM), (float)(GV13/GSUM), (float)(GV12/GSUM), (float)(GV11/GSUM),
    (float)(GV10/GSUM), (float)(GV9 /GSUM), (float)(GV8 /GSUM), (float)(GV7 /GSUM),
    (float)(GV6 /GSUM), (float)(GV5 /GSUM), (float)(GV4 /GSUM), (float)(GV3 /GSUM),
    (float)(GV2 /GSUM), (float)(GV1 /GSUM), (float)(GV0 /GSUM), (float)(GV1 /GSUM),
    (float)(GV2 /GSUM), (float)(GV3 /GSUM), (float)(GV4 /GSUM), (float)(GV5 /GSUM),
    (float)(GV6 /GSUM), (float)(GV7 /GSUM), (float)(GV8 /GSUM), (float)(GV9 /GSUM),
    (float)(GV10/GSUM), (float)(GV11/GSUM), (float)(GV12/GSUM), (float)(GV13/GSUM),
    (float)(GV14/GSUM)
};

__global__ void __launch_bounds__(256, 2)
gauss29_kernel(const float* __restrict__ x, float* __restrict__ out)
{
    extern __shared__ float S[];   // [IR][PITCH], rows quad-swizzled

    const int tid  = threadIdx.x;
    const int img  = blockIdx.x >> 2;      // 512 images
    const int tile = blockIdx.x & 3;       // 4 row-tiles per image
    const int y0   = tile * TY;

    const float* src = x   + (size_t)img * (IMG_H * IMG_W);
    float*       dst = out + (size_t)img * (IMG_H * IMG_W) + (size_t)y0 * IMG_W;

    // ---------------- Phase 1: load 92 rows with vertical reflect -----------
    #pragma unroll 4
    for (int u = tid; u < IR * 64; u += 256) {
        int r  = u >> 6;
        int c4 = u & 63;
        int gy = y0 - RAD + r;
        gy = (gy < 0) ? -gy : gy;
        gy = (gy > IMG_H - 1) ? (2 * (IMG_H - 1) - gy) : gy;
        float4 v = *((const float4*)(src + (size_t)gy * IMG_W) + c4);
        *(float4*)(&S[r * PITCH + swz(XOFF + c4 * 4)]) = v;
    }
    __syncthreads();

    // ---------------- Phase 2: vertical 29-tap conv, in place ---------------
    // Output local row j taps smem rows j..j+28.  Two chunks of 32 rows:
    // chunk reads rows [cbase, cbase+60), writes [cbase, cbase+32) post-barrier.
    const int xq = tid & 63;          // quad column 0..63
    const int yr = (tid >> 6) * 8;    // 0,8,16,24 within chunk
    const int colo = swz(XOFF + xq * 4);   // fixed swizzled in-row offset
    #pragma unroll 1
    for (int ch = 0; ch < 2; ++ch) {
        const int ybase = ch * 32 + yr;
        float4 acc[8];
        #pragma unroll
        for (int j = 0; j < 8; ++j) acc[j] = make_float4(0.f, 0.f, 0.f, 0.f);

        const float* col = &S[ybase * PITCH + colo];
        #pragma unroll
        for (int i = 0; i < 36; ++i) {
            float4 v = *(const float4*)(col + i * PITCH);
            #pragma unroll
            for (int j = 0; j < 8; ++j) {
                const int k = i - j;               // tap index
                if (k >= 0 && k <= 28) {
                    const float w = GW[k];
                    acc[j].x += w * v.x;
                    acc[j].y += w * v.y;
                    acc[j].z += w * v.z;
                    acc[j].w += w * v.w;
                }
            }
        }
        __syncthreads();   // all reads of this chunk done everywhere
        float* od = &S[ybase * PITCH + colo];
        #pragma unroll
        for (int j = 0; j < 8; ++j)
            *(float4*)(od + j * PITCH) = acc[j];
        __syncthreads();   // writes visible before next chunk reads
    }

    // ---------------- Phase 2.5: horizontal reflected halo ------------------
    // Fill float cols [0,16) (xi=-16..-1 -> x=16..1) and [272,288)
    // (xi=256..271 -> x=254..239) for the 64 intermediate rows.
    #pragma unroll 1
    for (int u = tid; u < TY * 32; u += 256) {
        int r = u >> 5;
        int p = u & 31;
        int colidx, xsrc;
        if (p < 16) { colidx = p;                 xsrc = 16 - p;      }
        else        { int q = p - 16; colidx = XOFF + 256 + q; xsrc = 254 - q; }
        S[r * PITCH + swz(colidx)] = S[r * PITCH + swz(XOFF + xsrc)];
    }
    __syncthreads();

    // ---------------- Phase 3: horizontal 29-tap conv + store ---------------
    // One warp per full 256-px row; lane covers 8 consecutive px.
    // Window = 10 float4 (40 floats, offsets o = 8*lane + 4t, t=0..9);
    // XOR-4 swizzle makes the 32B lane stride conflict-free per LDS.128 phase.
    const int lane = tid & 31;
    const int warp = tid >> 5;        // 0..7
    #pragma unroll 1
    for (int it = 0; it < 8; ++it) {
        const int row = warp * 8 + it;       // 0..63
        const float* rb = &S[row * PITCH];

        // f[i] = value at xi = 8*lane - 16 + i   (xi = x - XOFF offset space)
        float f[40];
        #pragma unroll
        for (int t = 0; t < 10; ++t) {
            float4 v = *(const float4*)(rb + swz(8 * lane + 4 * t));
            f[t * 4 + 0] = v.x; f[t * 4 + 1] = v.y;
            f[t * 4 + 2] = v.z; f[t * 4 + 3] = v.w;
        }

        float a[8];
        #pragma unroll
        for (int p = 0; p < 8; ++p) a[p] = 0.f;
        #pragma unroll
        for (int k = 0; k < 29; ++k) {
            const float w = GW[k];
            #pragma unroll
            for (int p = 0; p < 8; ++p)
                a[p] += w * f[p + k + 2];       // max index 7+28+2 = 37 < 40
        }

        float* op = dst + (size_t)row * IMG_W + lane * 8;
        *(float4*)(op + 0) = make_float4(a[0], a[1], a[2], a[3]);
        *(float4*)(op + 4) = make_float4(a[4], a[5], a[6], a[7]);
    }
}

extern "C" void kernel_launch(void* const* d_in, const int* in_sizes, int n_in,
                              void* d_out, int out_size)
{
    const float* x = (const float*)d_in[0];
    float* out = (float*)d_out;

    const int images = in_sizes[0] / (IMG_H * IMG_W);   // 512
    const int grid = images * 4;                        // 2048 CTAs

    cudaFuncSetAttribute(gauss29_kernel,
                         cudaFuncAttributeMaxDynamicSharedMemorySize,
                         SMEM_BYTES);
    gauss29_kernel<<<grid, 256, SMEM_BYTES>>>(x, out);
}

// round 10
// speedup vs baseline: 1.2545x; 1.1683x over previous
#include <cuda_runtime.h>
#include <cstddef>

// ---------------------------------------------------------------------------
// Depthwise Gaussian blur, sigma=7, K=29, reflect padding, (8,64,256,256) f32.
// Separable, fused single kernel.
// R7 change: TY 64 -> 32 (IR=60, smem 69KB) => 3 CTAs/SM, 24 warps (was 16).
// Phase 2 becomes a single in-place chunk (reads all 60 rows, then writes 32).
// Retains R4's 8 px/lane phase-3 + XOR-4 quad swizzle (conflict-free LDS.128).
// ---------------------------------------------------------------------------

#define IMG_H   256
#define IMG_W   256
#define TY      32            // output rows per tile
#define RAD     14
#define IR      (TY + 2*RAD)  // 60 input rows in smem
#define PITCH   288           // floats per smem row (16 halo + 256 + 16 halo)
#define XOFF    16            // float offset of x=0 within a smem row
#define SMEM_BYTES (IR * PITCH * 4)   // 69120

// Quad swizzle: XOR float-offset bit2 with bit5 (moves whole float4 blocks,
// bijective, within-row). Makes 32B-lane-stride LDS.128 conflict-free while
// keeping 16B-lane-stride accesses conflict-free too.
__device__ __forceinline__ int swz(int o) { return o ^ ((o & 32) >> 3); }

// Unnormalized Gaussian g(d) = exp(-d^2/98), d = 0..14 (double literals).
constexpr double GV0  = 1.0;
constexpr double GV1  = 0.98984780;
constexpr double GV2  = 0.96000544;
constexpr double GV3  = 0.91225408;
constexpr double GV4  = 0.84936582;
constexpr double GV5  = 0.77483743;
constexpr double GV6  = 0.69256933;
constexpr double GV7  = 0.60653066;
constexpr double GV8  = 0.52045018;
constexpr double GV9  = 0.43756464;
constexpr double GV10 = 0.36044780;
constexpr double GV11 = 0.29092383;
constexpr double GV12 = 0.23006630;
constexpr double GV13 = 0.17826390;
constexpr double GV14 = 0.13533528;

constexpr double GSUM = GV0 + 2.0*(GV1+GV2+GV3+GV4+GV5+GV6+GV7+GV8+GV9+GV10+GV11+GV12+GV13+GV14);

__device__ constexpr float GW[29] = {
    (float)(GV14/GSUM), (float)(GV13/GSUM), (float)(GV12/GSUM), (float)(GV11/GSUM),
    (float)(GV10/GSUM), (float)(GV9 /GSUM), (float)(GV8 /GSUM), (float)(GV7 /GSUM),
    (float)(GV6 /GSUM), (float)(GV5 /GSUM), (float)(GV4 /GSUM), (float)(GV3 /GSUM),
    (float)(GV2 /GSUM), (float)(GV1 /GSUM), (float)(GV0 /GSUM), (float)(GV1 /GSUM),
    (float)(GV2 /GSUM), (float)(GV3 /GSUM), (float)(GV4 /GSUM), (float)(GV5 /GSUM),
    (float)(GV6 /GSUM), (float)(GV7 /GSUM), (float)(GV8 /GSUM), (float)(GV9 /GSUM),
    (float)(GV10/GSUM), (float)(GV11/GSUM), (float)(GV12/GSUM), (float)(GV13/GSUM),
    (float)(GV14/GSUM)
};

__global__ void __launch_bounds__(256, 3)
gauss29_kernel(const float* __restrict__ x, float* __restrict__ out)
{
    extern __shared__ float S[];   // [IR][PITCH], rows quad-swizzled

    const int tid  = threadIdx.x;
    const int img  = blockIdx.x >> 3;      // 512 images
    const int tile = blockIdx.x & 7;       // 8 row-tiles per image
    const int y0   = tile * TY;

    const float* src = x   + (size_t)img * (IMG_H * IMG_W);
    float*       dst = out + (size_t)img * (IMG_H * IMG_W) + (size_t)y0 * IMG_W;

    // ---------------- Phase 1: load 60 rows with vertical reflect -----------
    // 60 rows * 64 quads = 3840 float4 loads; 15 per thread, coalesced.
    #pragma unroll 5
    for (int u = tid; u < IR * 64; u += 256) {
        int r  = u >> 6;
        int c4 = u & 63;
        int gy = y0 - RAD + r;
        gy = (gy < 0) ? -gy : gy;
        gy = (gy > IMG_H - 1) ? (2 * (IMG_H - 1) - gy) : gy;
        float4 v = *((const float4*)(src + (size_t)gy * IMG_W) + c4);
        *(float4*)(&S[r * PITCH + swz(XOFF + c4 * 4)]) = v;
    }
    __syncthreads();

    // ---------------- Phase 2: vertical 29-tap conv, in place ---------------
    // Single chunk: each thread computes 8 output rows (yr..yr+7), reading
    // smem rows yr..yr+35 (all <= 59). After the barrier it overwrites rows
    // 0..31, which no thread reads again (phase 3 reads only rows < TY).
    const int xq = tid & 63;          // quad column 0..63
    const int yr = (tid >> 6) * 8;    // 0,8,16,24
    const int colo = swz(XOFF + xq * 4);   // fixed swizzled in-row offset
    {
        float4 acc[8];
        #pragma unroll
        for (int j = 0; j < 8; ++j) acc[j] = make_float4(0.f, 0.f, 0.f, 0.f);

        const float* col = &S[yr * PITCH + colo];
        #pragma unroll
        for (int i = 0; i < 36; ++i) {
            float4 v = *(const float4*)(col + i * PITCH);
            #pragma unroll
            for (int j = 0; j < 8; ++j) {
                const int k = i - j;               // tap index
                if (k >= 0 && k <= 28) {
                    const float w = GW[k];
                    acc[j].x += w * v.x;
                    acc[j].y += w * v.y;
                    acc[j].z += w * v.z;
                    acc[j].w += w * v.w;
                }
            }
        }
        __syncthreads();   // all reads done everywhere
        float* od = &S[yr * PITCH + colo];
        #pragma unroll
        for (int j = 0; j < 8; ++j)
            *(float4*)(od + j * PITCH) = acc[j];
        __syncthreads();   // writes visible before phases 2.5/3 read
    }

    // ---------------- Phase 2.5: horizontal reflected halo ------------------
    // Fill float cols [0,16) (xi=-16..-1 -> x=16..1) and [272,288)
    // (xi=256..271 -> x=254..239) for the 32 intermediate rows.
    #pragma unroll 4
    for (int u = tid; u < TY * 32; u += 256) {
        int r = u >> 5;
        int p = u & 31;
        int colidx, xsrc;
        if (p < 16) { colidx = p;                 xsrc = 16 - p;      }
        else        { int q = p - 16; colidx = XOFF + 256 + q; xsrc = 254 - q; }
        S[r * PITCH + swz(colidx)] = S[r * PITCH + swz(XOFF + xsrc)];
    }
    __syncthreads();

    // ---------------- Phase 3: horizontal 29-tap conv + store ---------------
    // One warp per full 256-px row; lane covers 8 consecutive px.
    // Window = 10 float4 (40 floats, offsets o = 8*lane + 4t, t=0..9);
    // XOR-4 swizzle makes the 32B lane stride conflict-free per LDS.128 phase.
    const int lane = tid & 31;
    const int warp = tid >> 5;        // 0..7
    #pragma unroll 1
    for (int it = 0; it < 4; ++it) {
        const int row = warp * 4 + it;       // 0..31
        const float* rb = &S[row * PITCH];

        // f[i] = value at xi = 8*lane - 16 + i   (xi = x - XOFF offset space)
        float f[40];
        #pragma unroll
        for (int t = 0; t < 10; ++t) {
            float4 v = *(const float4*)(rb + swz(8 * lane + 4 * t));
            f[t * 4 + 0] = v.x; f[t * 4 + 1] = v.y;
            f[t * 4 + 2] = v.z; f[t * 4 + 3] = v.w;
        }

        float a[8];
        #pragma unroll
        for (int p = 0; p < 8; ++p) a[p] = 0.f;
        #pragma unroll
        for (int k = 0; k < 29; ++k) {
            const float w = GW[k];
            #pragma unroll
            for (int p = 0; p < 8; ++p)
                a[p] += w * f[p + k + 2];       // max index 7+28+2 = 37 < 40
        }

        float* op = dst + (size_t)row * IMG_W + lane * 8;
        *(float4*)(op + 0) = make_float4(a[0], a[1], a[2], a[3]);
        *(float4*)(op + 4) = make_float4(a[4], a[5], a[6], a[7]);
    }
}

extern "C" void kernel_launch(void* const* d_in, const int* in_sizes, int n_in,
                              void* d_out, int out_size)
{
    const float* x = (const float*)d_in[0];
    float* out = (float*)d_out;

    const int images = in_sizes[0] / (IMG_H * IMG_W);   // 512
    const int grid = images * 8;                        // 4096 CTAs

    cudaFuncSetAttribute(gauss29_kernel,
                         cudaFuncAttributeMaxDynamicSharedMemorySize,
                         SMEM_BYTES);
    gauss29_kernel<<<grid, 256, SMEM_BYTES>>>(x, out);
}